// round 14
// baseline (speedup 1.0000x reference)
#include <cuda_runtime.h>
#include <cuda_fp16.h>
#include <math.h>
#include <cstdint>

// ---------------- problem constants ----------------
#define PB 2
#define PT 2048
#define PE 1024
#define PH 16
#define PD 64
#define PV 32000
#define PM (PB*PT)            // 4096
#define QKVN 3072
#define BTV ((size_t)PM*PV)
#define NBL (PV/128)          // 250 N-blocks in logits gemm
#define NB4 (NBL*2)           // 500 partials per row

// ---------------- scratch (__device__ globals) ----------------
__device__ __half g_xh[(size_t)PM*PE],  g_xl[(size_t)PM*PE];
__device__ __half g_wqkv[(size_t)QKVN*PE];
__device__ __half g_wo[(size_t)PV*PE];
__device__ __half g_oh[(size_t)PM*PE];
__device__ float  g_qkv[(size_t)PM*QKVN];
__device__ float  g_bias3[QKVN];
__device__ float  g_rowloss[PM];
__device__ float2 g_lsepart[(size_t)PM*NB4];

// ---------------- helpers ----------------
__device__ __forceinline__ uint32_t smem_u32(const void* p) {
    uint32_t a;
    asm("{ .reg .u64 t; cvta.to.shared.u64 t, %1; cvt.u32.u64 %0, t; }" : "=r"(a) : "l"(p));
    return a;
}
__device__ __forceinline__ void cp16(uint32_t dst, const void* src) {
    asm volatile("cp.async.cg.shared.global [%0], [%1], 16;" :: "r"(dst), "l"(src) : "memory");
}
#define CP_COMMIT() asm volatile("cp.async.commit_group;" ::: "memory")
#define CP_WAIT(n)  asm volatile("cp.async.wait_group %0;" :: "n"(n) : "memory")

#define LDSM4(r0,r1,r2,r3,addr) \
    asm volatile("ldmatrix.sync.aligned.m8n8.x4.shared.b16 {%0,%1,%2,%3}, [%4];" \
        : "=r"(r0),"=r"(r1),"=r"(r2),"=r"(r3) : "r"(addr))
#define LDSM4T(r0,r1,r2,r3,addr) \
    asm volatile("ldmatrix.sync.aligned.m8n8.x4.trans.shared.b16 {%0,%1,%2,%3}, [%4];" \
        : "=r"(r0),"=r"(r1),"=r"(r2),"=r"(r3) : "r"(addr))

#define MMAF16(c, a, b0, b1) \
    asm volatile("mma.sync.aligned.m16n8k16.row.col.f32.f16.f16.f32 " \
        "{%0,%1,%2,%3}, {%4,%5,%6,%7}, {%8,%9}, {%0,%1,%2,%3};" \
        : "+f"((c)[0]), "+f"((c)[1]), "+f"((c)[2]), "+f"((c)[3]) \
        : "r"((a)[0]), "r"((a)[1]), "r"((a)[2]), "r"((a)[3]), "r"(b0), "r"(b1))

__device__ __forceinline__ uint32_t hpack(float x, float y) {
    __half2 h = __floats2half2_rn(x, y);
    return *(uint32_t*)&h;
}
__device__ __forceinline__ uint32_t lpack(float x, float y) {
    float hx = __half2float(__float2half(x));
    float hy = __half2float(__float2half(y));
    __half2 h = __floats2half2_rn(x - hx, y - hy);
    return *(uint32_t*)&h;
}

// ---------------- embed + fp16 hi/lo split ----------------
__global__ void embed_split(const int* __restrict__ tokens,
                            const float* __restrict__ tok_table,
                            const float* __restrict__ pos_emb,
                            __half* __restrict__ xh, __half* __restrict__ xl)
{
    int i4 = blockIdx.x * blockDim.x + threadIdx.x;
    int row = i4 >> 8, e4 = i4 & 255;
    int t = row & (PT - 1);
    float4 a = *(const float4*)(tok_table + (size_t)tokens[row] * PE + e4 * 4);
    float4 b = *(const float4*)(pos_emb + (size_t)t * PE + e4 * 4);
    float x0 = a.x + b.x, x1 = a.y + b.y, x2 = a.z + b.z, x3 = a.w + b.w;
    ((uint2*)xh)[i4] = make_uint2(hpack(x0, x1), hpack(x2, x3));
    ((uint2*)xl)[i4] = make_uint2(lpack(x0, x1), lpack(x2, x3));
}

__global__ void convW(const float* __restrict__ src, __half* __restrict__ dst, int n4)
{
    int i4 = blockIdx.x * blockDim.x + threadIdx.x;
    if (i4 >= n4) return;
    float4 v = ((const float4*)src)[i4];
    ((uint2*)dst)[i4] = make_uint2(hpack(v.x, v.y), hpack(v.z, v.w));
}

__global__ void pack_bias(const float* __restrict__ bq, const float* __restrict__ bk,
                          const float* __restrict__ bv, float* __restrict__ b3)
{
    int i = blockIdx.x * blockDim.x + threadIdx.x;
    if (i < 1024)       b3[i] = bq[i];
    else if (i < 2048)  b3[i] = bk[i - 1024];
    else if (i < QKVN)  b3[i] = bv[i - 2048];
}

// ---------------- common config ----------------
#define BM 128
#define BN 128
#define BK 32
#define KE 1024
#define STAGES 4
#define TILE_B (BM*BK*2)
#define NCHUNK (KE/BK)
__device__ __forceinline__ uint32_t swz(uint32_t base, int r, int c16) {
    return base + r * 64 + ((c16 ^ ((r >> 1) & 3)) << 4);
}

// ---------------- QKV GEMM: 128x128 CTA, 4 warps, 64x64 warp tile, 2-product ----------
#define SSTAGE2 (3*TILE_B)
#define GSMEM2 (STAGES*SSTAGE2)

__global__ __launch_bounds__(128, 2)
void gemm_fp16_2p(const __half* __restrict__ Ah, const __half* __restrict__ Al,
                  const __half* __restrict__ Bw,
                  const float* __restrict__ bias, float* __restrict__ C, int N)
{
    extern __shared__ char smem[];
    uint32_t sb = smem_u32(smem);
    int tid = threadIdx.x;
    int lane = tid & 31, wid = tid >> 5;
    int wm = wid >> 1, wn = wid & 1;         // 2 x 2 warps, warp tile 64 x 64
    int row0 = blockIdx.x * BM;
    int col0 = blockIdx.y * BN;

    const __half* Ahg = Ah + (size_t)row0 * KE;
    const __half* Alg = Al + (size_t)row0 * KE;
    const __half* Bg  = Bw + (size_t)col0 * KE;

    float acc[4][8][4];
#pragma unroll
    for (int i = 0; i < 4; i++)
#pragma unroll
        for (int j = 0; j < 8; j++)
#pragma unroll
            for (int q = 0; q < 4; q++) acc[i][j][q] = 0.f;

    // 1536 16B-units per stage / 128 thr = 12 per thread
#define STAGE_LOAD2(stageBase, k0)                                             \
    do {                                                                       \
        _Pragma("unroll")                                                      \
        for (int j = 0; j < 12; j++) {                                         \
            int u = tid + 128 * j;                                             \
            int p = u >> 9, ix = u & 511;                                      \
            int r = ix >> 2, c16 = ix & 3;                                     \
            const __half* src = (p == 0 ? Ahg : (p == 1 ? Alg : Bg));          \
            cp16(swz(sb + (stageBase), r, c16) + p * TILE_B,                   \
                 src + (size_t)r * KE + (k0) + c16 * 8);                       \
        }                                                                      \
    } while (0)

#pragma unroll
    for (int s = 0; s < STAGES - 1; s++) {
        STAGE_LOAD2(s * SSTAGE2, s * BK);
        CP_COMMIT();
    }

    for (int kt = 0; kt < NCHUNK; kt++) {
        CP_WAIT(STAGES - 2);
        __syncthreads();
        int pf = kt + STAGES - 1;
        if (pf < NCHUNK) STAGE_LOAD2((pf & (STAGES - 1)) * SSTAGE2, pf * BK);
        CP_COMMIT();

        uint32_t stB = sb + (kt & (STAGES - 1)) * SSTAGE2;
        uint32_t aHB = stB, aLB = stB + TILE_B, bB = stB + 2 * TILE_B;
#pragma unroll
        for (int ks = 0; ks < 2; ks++) {
            uint32_t rb[4][4];
#pragma unroll
            for (int ni = 0; ni < 4; ni++) {
                int r = wn * 64 + ni * 16 + (lane & 7) + ((lane >> 4) & 1) * 8;
                int c16 = ks * 2 + ((lane >> 3) & 1);
                LDSM4(rb[ni][0], rb[ni][1], rb[ni][2], rb[ni][3], swz(bB, r, c16));
            }
            int ar = wm * 64 + (lane & 15);
            int ac16 = ks * 2 + (lane >> 4);
            uint32_t raH[4][4], raL[4][4];
#pragma unroll
            for (int mi = 0; mi < 4; mi++) {
                LDSM4(raH[mi][0], raH[mi][1], raH[mi][2], raH[mi][3],
                      swz(aHB, ar + mi * 16, ac16));
                LDSM4(raL[mi][0], raL[mi][1], raL[mi][2], raL[mi][3],
                      swz(aLB, ar + mi * 16, ac16));
            }
#pragma unroll
            for (int mi = 0; mi < 4; mi++)
#pragma unroll
                for (int nj = 0; nj < 8; nj++) {
                    uint32_t b0 = rb[nj >> 1][(nj & 1) * 2];
                    uint32_t b1 = rb[nj >> 1][(nj & 1) * 2 + 1];
                    MMAF16(acc[mi][nj], raH[mi], b0, b1);
                    MMAF16(acc[mi][nj], raL[mi], b0, b1);
                }
        }
    }

    int g = lane >> 2, tg = lane & 3;
#pragma unroll
    for (int mi = 0; mi < 4; mi++) {
        int r = row0 + wm * 64 + mi * 16 + g;
#pragma unroll
        for (int nj = 0; nj < 8; nj++) {
            int c = col0 + wn * 64 + nj * 8 + tg * 2;
            float bx = bias[c], by = bias[c + 1];
            *(float2*)(C + (size_t)r * N + c) =
                make_float2(acc[mi][nj][0] + bx, acc[mi][nj][1] + by);
            *(float2*)(C + (size_t)(r + 8) * N + c) =
                make_float2(acc[mi][nj][2] + bx, acc[mi][nj][3] + by);
        }
    }
}

// ---------------- logits GEMM: 128x128 CTA, 4 warps, 64x64 warp tile, fused lse ----------
#define SSTAGE1 (2*TILE_B)
#define GSMEM1 (STAGES*SSTAGE1)     // 65536

__global__ __launch_bounds__(128, 2)
void gemm_fp16_1p(const __half* __restrict__ Aw, const __half* __restrict__ Bw,
                  const float* __restrict__ bias, float* __restrict__ C,
                  float2* __restrict__ lsep)
{
    extern __shared__ char smem[];
    uint32_t sb = smem_u32(smem);
    int tid = threadIdx.x;
    int lane = tid & 31, wid = tid >> 5;
    int wm = wid >> 1, wn = wid & 1;          // 2 x 2 warps, warp tile 64 x 64
    int row0 = blockIdx.x * BM;
    int col0 = blockIdx.y * BN;

    const __half* Ag = Aw + (size_t)row0 * KE;
    const __half* Bg = Bw + (size_t)col0 * KE;

    float acc[4][8][4];
#pragma unroll
    for (int i = 0; i < 4; i++)
#pragma unroll
        for (int j = 0; j < 8; j++)
#pragma unroll
            for (int q = 0; q < 4; q++) acc[i][j][q] = 0.f;

#define STAGE_LOAD1(stageBase, k0)                                             \
    do {                                                                       \
        _Pragma("unroll")                                                      \
        for (int j = 0; j < 8; j++) {                                          \
            int u = tid + 128 * j;                                             \
            int p = u >> 9, ix = u & 511;                                      \
            int r = ix >> 2, c16 = ix & 3;                                     \
            const __half* src = (p == 0 ? Ag : Bg);                            \
            cp16(swz(sb + (stageBase), r, c16) + p * TILE_B,                   \
                 src + (size_t)r * KE + (k0) + c16 * 8);                       \
        }                                                                      \
    } while (0)

#pragma unroll
    for (int s = 0; s < STAGES - 1; s++) {
        STAGE_LOAD1(s * SSTAGE1, s * BK);
        CP_COMMIT();
    }

    for (int kt = 0; kt < NCHUNK; kt++) {
        CP_WAIT(STAGES - 2);
        __syncthreads();
        int pf = kt + STAGES - 1;
        if (pf < NCHUNK) STAGE_LOAD1((pf & (STAGES - 1)) * SSTAGE1, pf * BK);
        CP_COMMIT();

        uint32_t stB = sb + (kt & (STAGES - 1)) * SSTAGE1;
        uint32_t aB = stB, bB = stB + TILE_B;
#pragma unroll
        for (int ks = 0; ks < 2; ks++) {
            uint32_t rb[4][4];
#pragma unroll
            for (int ni = 0; ni < 4; ni++) {
                int r = wn * 64 + ni * 16 + (lane & 7) + ((lane >> 4) & 1) * 8;
                int c16 = ks * 2 + ((lane >> 3) & 1);
                LDSM4(rb[ni][0], rb[ni][1], rb[ni][2], rb[ni][3], swz(bB, r, c16));
            }
            uint32_t ra[4][4];
            int ar = wm * 64 + (lane & 15);
            int ac16 = ks * 2 + (lane >> 4);
#pragma unroll
            for (int mi = 0; mi < 4; mi++)
                LDSM4(ra[mi][0], ra[mi][1], ra[mi][2], ra[mi][3],
                      swz(aB, ar + mi * 16, ac16));
#pragma unroll
            for (int mi = 0; mi < 4; mi++)
#pragma unroll
                for (int nj = 0; nj < 8; nj++)
                    MMAF16(acc[mi][nj], ra[mi],
                           rb[nj >> 1][(nj & 1) * 2], rb[nj >> 1][(nj & 1) * 2 + 1]);
        }
    }

    // epilogue: bias add, streaming store, fused per-row lse partial (64-col band)
    int g = lane >> 2, tg = lane & 3;
    int pslot = blockIdx.y * 2 + wn;
#pragma unroll
    for (int mi = 0; mi < 4; mi++) {
        int r = row0 + wm * 64 + mi * 16 + g;
        float m0 = -INFINITY, m1 = -INFINITY;
#pragma unroll
        for (int nj = 0; nj < 8; nj++) {
            int c = col0 + wn * 64 + nj * 8 + tg * 2;
            float bx = bias[c], by = bias[c + 1];
            float v0 = acc[mi][nj][0] + bx, v1 = acc[mi][nj][1] + by;
            float v2 = acc[mi][nj][2] + bx, v3 = acc[mi][nj][3] + by;
            acc[mi][nj][0] = v0; acc[mi][nj][1] = v1;
            acc[mi][nj][2] = v2; acc[mi][nj][3] = v3;
            __stcs((float2*)(C + (size_t)r * PV + c), make_float2(v0, v1));
            __stcs((float2*)(C + (size_t)(r + 8) * PV + c), make_float2(v2, v3));
            m0 = fmaxf(m0, fmaxf(v0, v1));
            m1 = fmaxf(m1, fmaxf(v2, v3));
        }
        m0 = fmaxf(m0, __shfl_xor_sync(~0u, m0, 1));
        m0 = fmaxf(m0, __shfl_xor_sync(~0u, m0, 2));
        m1 = fmaxf(m1, __shfl_xor_sync(~0u, m1, 1));
        m1 = fmaxf(m1, __shfl_xor_sync(~0u, m1, 2));
        float s0 = 0.f, s1 = 0.f;
#pragma unroll
        for (int nj = 0; nj < 8; nj++) {
            s0 += __expf(acc[mi][nj][0] - m0) + __expf(acc[mi][nj][1] - m0);
            s1 += __expf(acc[mi][nj][2] - m1) + __expf(acc[mi][nj][3] - m1);
        }
        s0 += __shfl_xor_sync(~0u, s0, 1); s0 += __shfl_xor_sync(~0u, s0, 2);
        s1 += __shfl_xor_sync(~0u, s1, 1); s1 += __shfl_xor_sync(~0u, s1, 2);
        if (tg == 0) {
            lsep[(size_t)r * NB4 + pslot] = make_float2(m0, s0);
            lsep[(size_t)(r + 8) * NB4 + pslot] = make_float2(m1, s1);
        }
    }
}

// ---------------- tensor-core flash attention (reversed-q0 scheduling) ----------------
#define FA_QB 128
#define FA_KB 64
#define FSQ 0
#define FSK 16384
#define FSVH 24576
#define FSVL 32768
#define FSMEM 40960

__device__ __forceinline__ uint32_t swz8(uint32_t base, int r, int c16) {
    return base + r * 128 + ((c16 ^ (r & 7)) << 4);
}
__device__ __forceinline__ float mclamp(float x) { return fmaxf(x, -1e30f); }

__global__ __launch_bounds__(256, 2)
void attn_tc(const float* __restrict__ qkv, __half* __restrict__ oh)
{
    __shared__ __align__(1024) char sm[FSMEM];
    uint32_t sb = smem_u32(sm);
    int tid = threadIdx.x;
    int lane = tid & 31, w = tid >> 5;
    int g = lane >> 2, tg = lane & 3;
    int bh = blockIdx.y;
    int b = bh >> 4, h = bh & 15;
    int q0 = (gridDim.x - 1 - blockIdx.x) * FA_QB;   // heaviest blocks first

    const float* base = qkv + (size_t)b * PT * QKVN;

#pragma unroll
    for (int j = 0; j < 4; j++) {
        int u = tid + 256 * j;
        int r = u >> 3, c8 = u & 7;
        const float* qp = base + (size_t)(q0 + r) * QKVN + h * PD + c8 * 8;
        float4 a = ((const float4*)qp)[0];
        float4 bb = ((const float4*)qp)[1];
        *(uint4*)(sm + (swz8(FSQ, r, c8))) =
            make_uint4(hpack(a.x, a.y), hpack(a.z, a.w), hpack(bb.x, bb.y), hpack(bb.z, bb.w));
    }
    __syncthreads();

    uint32_t qf[4][4];
#pragma unroll
    for (int kk = 0; kk < 4; kk++) {
        int r = w * 16 + (lane & 15);
        int c16 = kk * 2 + (lane >> 4);
        LDSM4(qf[kk][0], qf[kk][1], qf[kk][2], qf[kk][3], sb + swz8(FSQ, r, c16));
    }
    __syncthreads();

    float O[8][4];
#pragma unroll
    for (int d = 0; d < 8; d++)
#pragma unroll
        for (int q = 0; q < 4; q++) O[d][q] = 0.f;
    float m0 = -INFINITY, m1 = -INFINITY, l0 = 0.f, l1 = 0.f;

    int t0 = q0 + w * 16 + g;
    int t1 = t0 + 8;
    int tmaxw = q0 + w * 16 + 15;
    int nkt = q0 / FA_KB + 2;

    for (int kt = 0; kt < nkt; kt++) {
        int s0 = kt * FA_KB;
        {
            int r = tid >> 2, cq = tid & 3;
            const float* kp = base + (size_t)(s0 + r) * QKVN + 1024 + h * PD + cq * 16;
            const float* vp = kp + 1024;
#pragma unroll
            for (int i = 0; i < 2; i++) {
                float4 a = ((const float4*)kp)[2 * i];
                float4 c = ((const float4*)kp)[2 * i + 1];
                *(uint4*)(sm + swz8(FSK, r, cq * 2 + i)) =
                    make_uint4(hpack(a.x, a.y), hpack(a.z, a.w), hpack(c.x, c.y), hpack(c.z, c.w));
                float4 va = ((const float4*)vp)[2 * i];
                float4 vc = ((const float4*)vp)[2 * i + 1];
                *(uint4*)(sm + swz8(FSVH, r, cq * 2 + i)) =
                    make_uint4(hpack(va.x, va.y), hpack(va.z, va.w), hpack(vc.x, vc.y), hpack(vc.z, vc.w));
                *(uint4*)(sm + swz8(FSVL, r, cq * 2 + i)) =
                    make_uint4(lpack(va.x, va.y), lpack(va.z, va.w), lpack(vc.x, vc.y), lpack(vc.z, vc.w));
            }
        }
        __syncthreads();

        if (s0 <= tmaxw) {
            float S[8][4];
#pragma unroll
            for (int nj = 0; nj < 8; nj++)
#pragma unroll
                for (int q = 0; q < 4; q++) S[nj][q] = 0.f;
#pragma unroll
            for (int njp = 0; njp < 4; njp++) {
#pragma unroll
                for (int kk = 0; kk < 4; kk++) {
                    uint32_t b0, b1, b2, b3;
                    int r = njp * 16 + (lane & 7) + ((lane >> 4) & 1) * 8;
                    int c16 = kk * 2 + ((lane >> 3) & 1);
                    LDSM4(b0, b1, b2, b3, sb + swz8(FSK, r, c16));
                    MMAF16(S[2 * njp], qf[kk], b0, b1);
                    MMAF16(S[2 * njp + 1], qf[kk], b2, b3);
                }
            }
            float mx0 = -INFINITY, mx1 = -INFINITY;
#pragma unroll
            for (int nj = 0; nj < 8; nj++) {
                int s = s0 + nj * 8 + 2 * tg;
                float v0 = S[nj][0], v1 = S[nj][1], v2 = S[nj][2], v3 = S[nj][3];
                if (s > t0 || v0 == 0.f) v0 = -INFINITY;
                if (s + 1 > t0 || v1 == 0.f) v1 = -INFINITY;
                if (s > t1 || v2 == 0.f) v2 = -INFINITY;
                if (s + 1 > t1 || v3 == 0.f) v3 = -INFINITY;
                S[nj][0] = v0; S[nj][1] = v1; S[nj][2] = v2; S[nj][3] = v3;
                mx0 = fmaxf(mx0, fmaxf(v0, v1));
                mx1 = fmaxf(mx1, fmaxf(v2, v3));
            }
            mx0 = fmaxf(mx0, __shfl_xor_sync(~0u, mx0, 1));
            mx0 = fmaxf(mx0, __shfl_xor_sync(~0u, mx0, 2));
            mx1 = fmaxf(mx1, __shfl_xor_sync(~0u, mx1, 1));
            mx1 = fmaxf(mx1, __shfl_xor_sync(~0u, mx1, 2));

            float mn0 = fmaxf(m0, mx0), mn1 = fmaxf(m1, mx1);
            float c0 = __expf(mclamp(m0) - mclamp(mn0));
            float c1 = __expf(mclamp(m1) - mclamp(mn1));
            float me0 = mclamp(mn0), me1 = mclamp(mn1);

            float rs0 = 0.f, rs1 = 0.f;
#pragma unroll
            for (int nj = 0; nj < 8; nj++) {
                float p0 = __expf(S[nj][0] - me0);
                float p1 = __expf(S[nj][1] - me0);
                float p2 = __expf(S[nj][2] - me1);
                float p3 = __expf(S[nj][3] - me1);
                S[nj][0] = p0; S[nj][1] = p1; S[nj][2] = p2; S[nj][3] = p3;
                rs0 += p0 + p1; rs1 += p2 + p3;
            }
            rs0 += __shfl_xor_sync(~0u, rs0, 1); rs0 += __shfl_xor_sync(~0u, rs0, 2);
            rs1 += __shfl_xor_sync(~0u, rs1, 1); rs1 += __shfl_xor_sync(~0u, rs1, 2);
            l0 = l0 * c0 + rs0; l1 = l1 * c1 + rs1;
            m0 = mn0; m1 = mn1;

#pragma unroll
            for (int d = 0; d < 8; d++) {
                O[d][0] *= c0; O[d][1] *= c0;
                O[d][2] *= c1; O[d][3] *= c1;
            }

#pragma unroll
            for (int sk = 0; sk < 4; sk++) {
                uint32_t aH[4], aL[4];
                aH[0] = hpack(S[2 * sk][0], S[2 * sk][1]);
                aH[1] = hpack(S[2 * sk][2], S[2 * sk][3]);
                aH[2] = hpack(S[2 * sk + 1][0], S[2 * sk + 1][1]);
                aH[3] = hpack(S[2 * sk + 1][2], S[2 * sk + 1][3]);
                aL[0] = lpack(S[2 * sk][0], S[2 * sk][1]);
                aL[1] = lpack(S[2 * sk][2], S[2 * sk][3]);
                aL[2] = lpack(S[2 * sk + 1][0], S[2 * sk + 1][1]);
                aL[3] = lpack(S[2 * sk + 1][2], S[2 * sk + 1][3]);
#pragma unroll
                for (int djp = 0; djp < 4; djp++) {
                    int r = sk * 16 + (lane & 15);
                    int c16 = djp * 2 + (lane >> 4);
                    uint32_t v0, v1, v2, v3;
                    LDSM4T(v0, v1, v2, v3, sb + swz8(FSVH, r, c16));
                    MMAF16(O[2 * djp], aH, v0, v1);
                    MMAF16(O[2 * djp + 1], aH, v2, v3);
                    MMAF16(O[2 * djp], aL, v0, v1);
                    MMAF16(O[2 * djp + 1], aL, v2, v3);
                    uint32_t w0, w1, w2, w3;
                    LDSM4T(w0, w1, w2, w3, sb + swz8(FSVL, r, c16));
                    MMAF16(O[2 * djp], aH, w0, w1);
                    MMAF16(O[2 * djp + 1], aH, w2, w3);
                }
            }
        }
        __syncthreads();
    }

    float inv0 = 1.f / (l0 * 8.0f);
    float inv1 = 1.f / (l1 * 8.0f);
    size_t r0 = (size_t)(b * PT + t0) * PE + h * PD;
    size_t r1 = (size_t)(b * PT + t1) * PE + h * PD;
#pragma unroll
    for (int dj = 0; dj < 8; dj++) {
        int c = dj * 8 + 2 * tg;
        *(uint32_t*)(oh + r0 + c) = hpack(O[dj][0] * inv0, O[dj][1] * inv0);
        *(uint32_t*)(oh + r1 + c) = hpack(O[dj][2] * inv1, O[dj][3] * inv1);
    }
}

// ---------------- loss: merge fused lse partials ----------------
__global__ __launch_bounds__(256)
void lse_reduce(const float2* __restrict__ lsep, const float* __restrict__ logits,
                const int* __restrict__ targets, float* __restrict__ rowloss)
{
    __shared__ float smx[256], ssx[256];
    int row = blockIdx.x, tid = threadIdx.x;
    const float2* pr = lsep + (size_t)row * NB4;
    float m = -INFINITY, s = 0.f;
    for (int i = tid; i < NB4; i += 256) {
        float2 p = pr[i];
        float mm = fmaxf(m, p.x);
        s = s * __expf(m - mm) + p.y * __expf(p.x - mm);
        m = mm;
    }
    smx[tid] = m; ssx[tid] = s; __syncthreads();
    for (int k = 128; k > 0; k >>= 1) {
        if (tid < k) {
            float m1 = smx[tid], s1 = ssx[tid], m2 = smx[tid + k], s2 = ssx[tid + k];
            float mm = fmaxf(m1, m2);
            smx[tid] = mm;
            ssx[tid] = s1 * __expf(m1 - mm) + s2 * __expf(m2 - mm);
        }
        __syncthreads();
    }
    if (tid == 0) {
        float lse = smx[0] + logf(ssx[0]);
        rowloss[row] = -(logits[(size_t)row * PV + targets[row]] - lse);
    }
}

__global__ __launch_bounds__(256)
void finloss_kernel(const float* __restrict__ rowloss, float* __restrict__ out_loss)
{
    __shared__ float red[256];
    int tid = threadIdx.x;
    float s = 0.f;
    for (int i = tid; i < PM; i += 256) s += rowloss[i];
    red[tid] = s; __syncthreads();
    for (int k = 128; k > 0; k >>= 1) { if (tid < k) red[tid] += red[tid+k]; __syncthreads(); }
    if (tid == 0) out_loss[0] = red[0] / (float)PM;
}

// ---------------- launch ----------------
extern "C" void kernel_launch(void* const* d_in, const int* in_sizes, int n_in,
                              void* d_out, int out_size)
{
    const int*   tokens    = (const int*)d_in[0];
    const int*   targets   = (const int*)d_in[1];
    const float* tok_table = (const float*)d_in[2];
    const float* pos_emb   = (const float*)d_in[3];
    const float* Wq = (const float*)d_in[4];  const float* bq = (const float*)d_in[5];
    const float* Wk = (const float*)d_in[6];  const float* bk = (const float*)d_in[7];
    const float* Wv = (const float*)d_in[8];  const float* bv = (const float*)d_in[9];
    const float* Wo = (const float*)d_in[10]; const float* bo = (const float*)d_in[11];
    float* out = (float*)d_out;

    __half *xh, *xl, *wqkv, *wo, *oh;
    float *qkv, *b3, *rl;
    float2 *lp;
    cudaGetSymbolAddress((void**)&xh,   g_xh);
    cudaGetSymbolAddress((void**)&xl,   g_xl);
    cudaGetSymbolAddress((void**)&wqkv, g_wqkv);
    cudaGetSymbolAddress((void**)&wo,   g_wo);
    cudaGetSymbolAddress((void**)&oh,   g_oh);
    cudaGetSymbolAddress((void**)&qkv,  g_qkv);
    cudaGetSymbolAddress((void**)&b3,   g_bias3);
    cudaGetSymbolAddress((void**)&rl,   g_rowloss);
    cudaGetSymbolAddress((void**)&lp,   g_lsepart);

    cudaFuncSetAttribute(gemm_fp16_2p, cudaFuncAttributeMaxDynamicSharedMemorySize, GSMEM2);
    cudaFuncSetAttribute(gemm_fp16_1p, cudaFuncAttributeMaxDynamicSharedMemorySize, GSMEM1);

    // 1) embed + fp16 hi/lo split of x
    embed_split<<<(PM * PE / 4) / 256, 256>>>(tokens, tok_table, pos_emb, xh, xl);

    // 2) weight converts + bias pack
    convW<<<(PE*PE/4)/256, 256>>>(Wq, wqkv,                   PE*PE/4);
    convW<<<(PE*PE/4)/256, 256>>>(Wk, wqkv + (size_t)PE*PE,   PE*PE/4);
    convW<<<(PE*PE/4)/256, 256>>>(Wv, wqkv + (size_t)2*PE*PE, PE*PE/4);
    convW<<<(int)(((size_t)PV*PE/4)/256), 256>>>(Wo, wo, (int)((size_t)PV*PE/4));
    pack_bias<<<QKVN/256, 256>>>(bq, bk, bv, b3);

    // 3) fused QKV GEMM (4-warp 64x64, 2-product split-A)
    gemm_fp16_2p<<<dim3(PM/BM, QKVN/BN), 128, GSMEM2>>>(xh, xl, wqkv, b3, qkv, QKVN);

    // 4) tensor-core flash attention -> oh (fp16)
    attn_tc<<<dim3(PT/FA_QB, PB*PH), 256>>>(qkv, oh);

    // 5) logits GEMM (4-warp 64x64 + fused lse, streaming stores) -> d_out
    gemm_fp16_1p<<<dim3(PM/BM, PV/BN), 128, GSMEM1>>>(oh, wo, bo, out, lp);

    // 6) loss from partials
    if ((size_t)out_size > BTV) {
        lse_reduce<<<PM, 256>>>(lp, out, targets, rl);
        finloss_kernel<<<1, 256>>>(rl, out + BTV);
    }
}

// round 15
// speedup vs baseline: 1.0093x; 1.0093x over previous
#include <cuda_runtime.h>
#include <cuda_fp16.h>
#include <math.h>
#include <cstdint>

// ---------------- problem constants ----------------
#define PB 2
#define PT 2048
#define PE 1024
#define PH 16
#define PD 64
#define PV 32000
#define PM (PB*PT)            // 4096
#define QKVN 3072
#define BTV ((size_t)PM*PV)
#define NBL (PV/128)          // 250 N-blocks in logits gemm
#define NB4 (NBL*2)           // 500 partials per row

// ---------------- scratch (__device__ globals) ----------------
__device__ __half g_xh[(size_t)PM*PE],  g_xl[(size_t)PM*PE];
__device__ __half g_wqkv[(size_t)QKVN*PE];
__device__ __half g_wo[(size_t)PV*PE];
__device__ __half g_oh[(size_t)PM*PE];
__device__ float  g_qkv[(size_t)PM*QKVN];
__device__ __half g_qh[(size_t)PM*PE];          // q fp16 plane
__device__ __half g_kh[(size_t)PM*PE];          // k fp16 plane
__device__ __half g_vh[(size_t)PM*PE];          // v hi plane
__device__ __half g_vl[(size_t)PM*PE];          // v lo plane
__device__ float  g_bias3[QKVN];
__device__ float  g_rowloss[PM];
__device__ float2 g_lsepart[(size_t)PM*NB4];

// ---------------- helpers ----------------
__device__ __forceinline__ uint32_t smem_u32(const void* p) {
    uint32_t a;
    asm("{ .reg .u64 t; cvta.to.shared.u64 t, %1; cvt.u32.u64 %0, t; }" : "=r"(a) : "l"(p));
    return a;
}
__device__ __forceinline__ void cp16(uint32_t dst, const void* src) {
    asm volatile("cp.async.cg.shared.global [%0], [%1], 16;" :: "r"(dst), "l"(src) : "memory");
}
#define CP_COMMIT() asm volatile("cp.async.commit_group;" ::: "memory")
#define CP_WAIT(n)  asm volatile("cp.async.wait_group %0;" :: "n"(n) : "memory")

#define LDSM4(r0,r1,r2,r3,addr) \
    asm volatile("ldmatrix.sync.aligned.m8n8.x4.shared.b16 {%0,%1,%2,%3}, [%4];" \
        : "=r"(r0),"=r"(r1),"=r"(r2),"=r"(r3) : "r"(addr))
#define LDSM4T(r0,r1,r2,r3,addr) \
    asm volatile("ldmatrix.sync.aligned.m8n8.x4.trans.shared.b16 {%0,%1,%2,%3}, [%4];" \
        : "=r"(r0),"=r"(r1),"=r"(r2),"=r"(r3) : "r"(addr))

#define MMAF16(c, a, b0, b1) \
    asm volatile("mma.sync.aligned.m16n8k16.row.col.f32.f16.f16.f32 " \
        "{%0,%1,%2,%3}, {%4,%5,%6,%7}, {%8,%9}, {%0,%1,%2,%3};" \
        : "+f"((c)[0]), "+f"((c)[1]), "+f"((c)[2]), "+f"((c)[3]) \
        : "r"((a)[0]), "r"((a)[1]), "r"((a)[2]), "r"((a)[3]), "r"(b0), "r"(b1))

__device__ __forceinline__ uint32_t hpack(float x, float y) {
    __half2 h = __floats2half2_rn(x, y);
    return *(uint32_t*)&h;
}
__device__ __forceinline__ uint32_t lpack(float x, float y) {
    float hx = __half2float(__float2half(x));
    float hy = __half2float(__float2half(y));
    __half2 h = __floats2half2_rn(x - hx, y - hy);
    return *(uint32_t*)&h;
}

// ---------------- embed + fp16 hi/lo split ----------------
__global__ void embed_split(const int* __restrict__ tokens,
                            const float* __restrict__ tok_table,
                            const float* __restrict__ pos_emb,
                            __half* __restrict__ xh, __half* __restrict__ xl)
{
    int i4 = blockIdx.x * blockDim.x + threadIdx.x;
    int row = i4 >> 8, e4 = i4 & 255;
    int t = row & (PT - 1);
    float4 a = *(const float4*)(tok_table + (size_t)tokens[row] * PE + e4 * 4);
    float4 b = *(const float4*)(pos_emb + (size_t)t * PE + e4 * 4);
    float x0 = a.x + b.x, x1 = a.y + b.y, x2 = a.z + b.z, x3 = a.w + b.w;
    ((uint2*)xh)[i4] = make_uint2(hpack(x0, x1), hpack(x2, x3));
    ((uint2*)xl)[i4] = make_uint2(lpack(x0, x1), lpack(x2, x3));
}

__global__ void convW(const float* __restrict__ src, __half* __restrict__ dst, int n4)
{
    int i4 = blockIdx.x * blockDim.x + threadIdx.x;
    if (i4 >= n4) return;
    float4 v = ((const float4*)src)[i4];
    ((uint2*)dst)[i4] = make_uint2(hpack(v.x, v.y), hpack(v.z, v.w));
}

__global__ void pack_bias(const float* __restrict__ bq, const float* __restrict__ bk,
                          const float* __restrict__ bv, float* __restrict__ b3)
{
    int i = blockIdx.x * blockDim.x + threadIdx.x;
    if (i < 1024)       b3[i] = bq[i];
    else if (i < 2048)  b3[i] = bk[i - 1024];
    else if (i < QKVN)  b3[i] = bv[i - 2048];
}

// ---------------- qkv -> fp16 planes (one-time convert, kills redundant staging work) ----
__global__ void qkv_split(const float* __restrict__ qkv,
                          __half* __restrict__ qh, __half* __restrict__ kh,
                          __half* __restrict__ vh, __half* __restrict__ vl)
{
    int i4 = blockIdx.x * blockDim.x + threadIdx.x;    // over M*PE/4
    int m = i4 >> 8, c4 = i4 & 255;
    const float* row = qkv + (size_t)m * QKVN + c4 * 4;
    float4 q = *(const float4*)(row);
    float4 k = *(const float4*)(row + 1024);
    float4 v = *(const float4*)(row + 2048);
    ((uint2*)qh)[i4] = make_uint2(hpack(q.x, q.y), hpack(q.z, q.w));
    ((uint2*)kh)[i4] = make_uint2(hpack(k.x, k.y), hpack(k.z, k.w));
    ((uint2*)vh)[i4] = make_uint2(hpack(v.x, v.y), hpack(v.z, v.w));
    ((uint2*)vl)[i4] = make_uint2(lpack(v.x, v.y), lpack(v.z, v.w));
}

// ---------------- common config ----------------
#define BM 128
#define BN 128
#define BK 32
#define KE 1024
#define STAGES 4
#define TILE_B (BM*BK*2)
#define NCHUNK (KE/BK)
__device__ __forceinline__ uint32_t swz(uint32_t base, int r, int c16) {
    return base + r * 64 + ((c16 ^ ((r >> 1) & 3)) << 4);
}

// ---------------- QKV GEMM: 128x128 CTA, 4 warps, 64x64 warp tile, 2-product ----------
#define SSTAGE2 (3*TILE_B)
#define GSMEM2 (STAGES*SSTAGE2)

__global__ __launch_bounds__(128, 2)
void gemm_fp16_2p(const __half* __restrict__ Ah, const __half* __restrict__ Al,
                  const __half* __restrict__ Bw,
                  const float* __restrict__ bias, float* __restrict__ C, int N)
{
    extern __shared__ char smem[];
    uint32_t sb = smem_u32(smem);
    int tid = threadIdx.x;
    int lane = tid & 31, wid = tid >> 5;
    int wm = wid >> 1, wn = wid & 1;         // 2 x 2 warps, warp tile 64 x 64
    int row0 = blockIdx.x * BM;
    int col0 = blockIdx.y * BN;

    const __half* Ahg = Ah + (size_t)row0 * KE;
    const __half* Alg = Al + (size_t)row0 * KE;
    const __half* Bg  = Bw + (size_t)col0 * KE;

    float acc[4][8][4];
#pragma unroll
    for (int i = 0; i < 4; i++)
#pragma unroll
        for (int j = 0; j < 8; j++)
#pragma unroll
            for (int q = 0; q < 4; q++) acc[i][j][q] = 0.f;

#define STAGE_LOAD2(stageBase, k0)                                             \
    do {                                                                       \
        _Pragma("unroll")                                                      \
        for (int j = 0; j < 12; j++) {                                         \
            int u = tid + 128 * j;                                             \
            int p = u >> 9, ix = u & 511;                                      \
            int r = ix >> 2, c16 = ix & 3;                                     \
            const __half* src = (p == 0 ? Ahg : (p == 1 ? Alg : Bg));          \
            cp16(swz(sb + (stageBase), r, c16) + p * TILE_B,                   \
                 src + (size_t)r * KE + (k0) + c16 * 8);                       \
        }                                                                      \
    } while (0)

#pragma unroll
    for (int s = 0; s < STAGES - 1; s++) {
        STAGE_LOAD2(s * SSTAGE2, s * BK);
        CP_COMMIT();
    }

    for (int kt = 0; kt < NCHUNK; kt++) {
        CP_WAIT(STAGES - 2);
        __syncthreads();
        int pf = kt + STAGES - 1;
        if (pf < NCHUNK) STAGE_LOAD2((pf & (STAGES - 1)) * SSTAGE2, pf * BK);
        CP_COMMIT();

        uint32_t stB = sb + (kt & (STAGES - 1)) * SSTAGE2;
        uint32_t aHB = stB, aLB = stB + TILE_B, bB = stB + 2 * TILE_B;
#pragma unroll
        for (int ks = 0; ks < 2; ks++) {
            uint32_t rb[4][4];
#pragma unroll
            for (int ni = 0; ni < 4; ni++) {
                int r = wn * 64 + ni * 16 + (lane & 7) + ((lane >> 4) & 1) * 8;
                int c16 = ks * 2 + ((lane >> 3) & 1);
                LDSM4(rb[ni][0], rb[ni][1], rb[ni][2], rb[ni][3], swz(bB, r, c16));
            }
            int ar = wm * 64 + (lane & 15);
            int ac16 = ks * 2 + (lane >> 4);
            uint32_t raH[4][4], raL[4][4];
#pragma unroll
            for (int mi = 0; mi < 4; mi++) {
                LDSM4(raH[mi][0], raH[mi][1], raH[mi][2], raH[mi][3],
                      swz(aHB, ar + mi * 16, ac16));
                LDSM4(raL[mi][0], raL[mi][1], raL[mi][2], raL[mi][3],
                      swz(aLB, ar + mi * 16, ac16));
            }
#pragma unroll
            for (int mi = 0; mi < 4; mi++)
#pragma unroll
                for (int nj = 0; nj < 8; nj++) {
                    uint32_t b0 = rb[nj >> 1][(nj & 1) * 2];
                    uint32_t b1 = rb[nj >> 1][(nj & 1) * 2 + 1];
                    MMAF16(acc[mi][nj], raH[mi], b0, b1);
                    MMAF16(acc[mi][nj], raL[mi], b0, b1);
                }
        }
    }

    int g = lane >> 2, tg = lane & 3;
#pragma unroll
    for (int mi = 0; mi < 4; mi++) {
        int r = row0 + wm * 64 + mi * 16 + g;
#pragma unroll
        for (int nj = 0; nj < 8; nj++) {
            int c = col0 + wn * 64 + nj * 8 + tg * 2;
            float bx = bias[c], by = bias[c + 1];
            *(float2*)(C + (size_t)r * N + c) =
                make_float2(acc[mi][nj][0] + bx, acc[mi][nj][1] + by);
            *(float2*)(C + (size_t)(r + 8) * N + c) =
                make_float2(acc[mi][nj][2] + bx, acc[mi][nj][3] + by);
        }
    }
}

// ---------------- logits GEMM: 128x128 CTA, 4 warps, 64x64 warp tile, fused lse ----------
#define SSTAGE1 (2*TILE_B)
#define GSMEM1 (STAGES*SSTAGE1)     // 65536

__global__ __launch_bounds__(128, 2)
void gemm_fp16_1p(const __half* __restrict__ Aw, const __half* __restrict__ Bw,
                  const float* __restrict__ bias, float* __restrict__ C,
                  float2* __restrict__ lsep)
{
    extern __shared__ char smem[];
    uint32_t sb = smem_u32(smem);
    int tid = threadIdx.x;
    int lane = tid & 31, wid = tid >> 5;
    int wm = wid >> 1, wn = wid & 1;          // 2 x 2 warps, warp tile 64 x 64
    int row0 = blockIdx.x * BM;
    int col0 = blockIdx.y * BN;

    const __half* Ag = Aw + (size_t)row0 * KE;
    const __half* Bg = Bw + (size_t)col0 * KE;

    float acc[4][8][4];
#pragma unroll
    for (int i = 0; i < 4; i++)
#pragma unroll
        for (int j = 0; j < 8; j++)
#pragma unroll
            for (int q = 0; q < 4; q++) acc[i][j][q] = 0.f;

#define STAGE_LOAD1(stageBase, k0)                                             \
    do {                                                                       \
        _Pragma("unroll")                                                      \
        for (int j = 0; j < 8; j++) {                                          \
            int u = tid + 128 * j;                                             \
            int p = u >> 9, ix = u & 511;                                      \
            int r = ix >> 2, c16 = ix & 3;                                     \
            const __half* src = (p == 0 ? Ag : Bg);                            \
            cp16(swz(sb + (stageBase), r, c16) + p * TILE_B,                   \
                 src + (size_t)r * KE + (k0) + c16 * 8);                       \
        }                                                                      \
    } while (0)

#pragma unroll
    for (int s = 0; s < STAGES - 1; s++) {
        STAGE_LOAD1(s * SSTAGE1, s * BK);
        CP_COMMIT();
    }

    for (int kt = 0; kt < NCHUNK; kt++) {
        CP_WAIT(STAGES - 2);
        __syncthreads();
        int pf = kt + STAGES - 1;
        if (pf < NCHUNK) STAGE_LOAD1((pf & (STAGES - 1)) * SSTAGE1, pf * BK);
        CP_COMMIT();

        uint32_t stB = sb + (kt & (STAGES - 1)) * SSTAGE1;
        uint32_t aB = stB, bB = stB + TILE_B;
#pragma unroll
        for (int ks = 0; ks < 2; ks++) {
            uint32_t rb[4][4];
#pragma unroll
            for (int ni = 0; ni < 4; ni++) {
                int r = wn * 64 + ni * 16 + (lane & 7) + ((lane >> 4) & 1) * 8;
                int c16 = ks * 2 + ((lane >> 3) & 1);
                LDSM4(rb[ni][0], rb[ni][1], rb[ni][2], rb[ni][3], swz(bB, r, c16));
            }
            uint32_t ra[4][4];
            int ar = wm * 64 + (lane & 15);
            int ac16 = ks * 2 + (lane >> 4);
#pragma unroll
            for (int mi = 0; mi < 4; mi++)
                LDSM4(ra[mi][0], ra[mi][1], ra[mi][2], ra[mi][3],
                      swz(aB, ar + mi * 16, ac16));
#pragma unroll
            for (int mi = 0; mi < 4; mi++)
#pragma unroll
                for (int nj = 0; nj < 8; nj++)
                    MMAF16(acc[mi][nj], ra[mi],
                           rb[nj >> 1][(nj & 1) * 2], rb[nj >> 1][(nj & 1) * 2 + 1]);
        }
    }

    // epilogue: bias add, streaming store, fused per-row lse partial (64-col band)
    int g = lane >> 2, tg = lane & 3;
    int pslot = blockIdx.y * 2 + wn;
#pragma unroll
    for (int mi = 0; mi < 4; mi++) {
        int r = row0 + wm * 64 + mi * 16 + g;
        float m0 = -INFINITY, m1 = -INFINITY;
#pragma unroll
        for (int nj = 0; nj < 8; nj++) {
            int c = col0 + wn * 64 + nj * 8 + tg * 2;
            float bx = bias[c], by = bias[c + 1];
            float v0 = acc[mi][nj][0] + bx, v1 = acc[mi][nj][1] + by;
            float v2 = acc[mi][nj][2] + bx, v3 = acc[mi][nj][3] + by;
            acc[mi][nj][0] = v0; acc[mi][nj][1] = v1;
            acc[mi][nj][2] = v2; acc[mi][nj][3] = v3;
            __stcs((float2*)(C + (size_t)r * PV + c), make_float2(v0, v1));
            __stcs((float2*)(C + (size_t)(r + 8) * PV + c), make_float2(v2, v3));
            m0 = fmaxf(m0, fmaxf(v0, v1));
            m1 = fmaxf(m1, fmaxf(v2, v3));
        }
        m0 = fmaxf(m0, __shfl_xor_sync(~0u, m0, 1));
        m0 = fmaxf(m0, __shfl_xor_sync(~0u, m0, 2));
        m1 = fmaxf(m1, __shfl_xor_sync(~0u, m1, 1));
        m1 = fmaxf(m1, __shfl_xor_sync(~0u, m1, 2));
        float s0 = 0.f, s1 = 0.f;
#pragma unroll
        for (int nj = 0; nj < 8; nj++) {
            s0 += __expf(acc[mi][nj][0] - m0) + __expf(acc[mi][nj][1] - m0);
            s1 += __expf(acc[mi][nj][2] - m1) + __expf(acc[mi][nj][3] - m1);
        }
        s0 += __shfl_xor_sync(~0u, s0, 1); s0 += __shfl_xor_sync(~0u, s0, 2);
        s1 += __shfl_xor_sync(~0u, s1, 1); s1 += __shfl_xor_sync(~0u, s1, 2);
        if (tg == 0) {
            lsep[(size_t)r * NB4 + pslot] = make_float2(m0, s0);
            lsep[(size_t)(r + 8) * NB4 + pslot] = make_float2(m1, s1);
        }
    }
}

// ---------------- tensor-core flash attention (fp16 plane staging) ----------------
#define FA_QB 128
#define FA_KB 64
#define FSQ 0
#define FSK 16384
#define FSVH 24576
#define FSVL 32768
#define FSMEM 40960

__device__ __forceinline__ uint32_t swz8(uint32_t base, int r, int c16) {
    return base + r * 128 + ((c16 ^ (r & 7)) << 4);
}
__device__ __forceinline__ float mclamp(float x) { return fmaxf(x, -1e30f); }

__global__ __launch_bounds__(256, 2)
void attn_tc(const __half* __restrict__ qh, const __half* __restrict__ kh,
             const __half* __restrict__ vh, const __half* __restrict__ vl,
             __half* __restrict__ oh)
{
    __shared__ __align__(1024) char sm[FSMEM];
    uint32_t sb = smem_u32(sm);
    int tid = threadIdx.x;
    int lane = tid & 31, w = tid >> 5;
    int g = lane >> 2, tg = lane & 3;
    int bh = blockIdx.y;
    int b = bh >> 4, h = bh & 15;
    int q0 = (gridDim.x - 1 - blockIdx.x) * FA_QB;   // heaviest blocks first

    const __half* qb = qh + ((size_t)b * PT) * PE + h * PD;
    const __half* kb = kh + ((size_t)b * PT) * PE + h * PD;
    const __half* vhb = vh + ((size_t)b * PT) * PE + h * PD;
    const __half* vlb = vl + ((size_t)b * PT) * PE + h * PD;

    // ---- stage Q (fp16 copy): 128 rows x 8 uint4 ----
#pragma unroll
    for (int j = 0; j < 4; j++) {
        int u = tid + 256 * j;
        int r = u >> 3, c8 = u & 7;
        uint4 v = *(const uint4*)(qb + (size_t)(q0 + r) * PE + c8 * 8);
        *(uint4*)(sm + swz8(FSQ, r, c8)) = v;
    }
    __syncthreads();

    uint32_t qf[4][4];
#pragma unroll
    for (int kk = 0; kk < 4; kk++) {
        int r = w * 16 + (lane & 15);
        int c16 = kk * 2 + (lane >> 4);
        LDSM4(qf[kk][0], qf[kk][1], qf[kk][2], qf[kk][3], sb + swz8(FSQ, r, c16));
    }
    __syncthreads();

    float O[8][4];
#pragma unroll
    for (int d = 0; d < 8; d++)
#pragma unroll
        for (int q = 0; q < 4; q++) O[d][q] = 0.f;
    float m0 = -INFINITY, m1 = -INFINITY, l0 = 0.f, l1 = 0.f;

    int t0 = q0 + w * 16 + g;
    int t1 = t0 + 8;
    int tmaxw = q0 + w * 16 + 15;
    int nkt = q0 / FA_KB + 2;

    for (int kt = 0; kt < nkt; kt++) {
        int s0 = kt * FA_KB;
        // ---- stage K/Vh/Vl (fp16 copies): 3 planes x 512 uint4-units / 256 thr ----
#pragma unroll
        for (int j = 0; j < 6; j++) {
            int u = tid + 256 * j;
            int p = u >> 9, ix = u & 511;
            int r = ix >> 3, c8 = ix & 7;
            const __half* src = (p == 0 ? kb : (p == 1 ? vhb : vlb));
            uint4 v = *(const uint4*)(src + (size_t)(s0 + r) * PE + c8 * 8);
            *(uint4*)(sm + swz8(FSK + p * 8192, r, c8)) = v;
        }
        __syncthreads();

        if (s0 <= tmaxw) {
            float S[8][4];
#pragma unroll
            for (int nj = 0; nj < 8; nj++)
#pragma unroll
                for (int q = 0; q < 4; q++) S[nj][q] = 0.f;
#pragma unroll
            for (int njp = 0; njp < 4; njp++) {
#pragma unroll
                for (int kk = 0; kk < 4; kk++) {
                    uint32_t b0, b1, b2, b3;
                    int r = njp * 16 + (lane & 7) + ((lane >> 4) & 1) * 8;
                    int c16 = kk * 2 + ((lane >> 3) & 1);
                    LDSM4(b0, b1, b2, b3, sb + swz8(FSK, r, c16));
                    MMAF16(S[2 * njp], qf[kk], b0, b1);
                    MMAF16(S[2 * njp + 1], qf[kk], b2, b3);
                }
            }
            float mx0 = -INFINITY, mx1 = -INFINITY;
#pragma unroll
            for (int nj = 0; nj < 8; nj++) {
                int s = s0 + nj * 8 + 2 * tg;
                float v0 = S[nj][0], v1 = S[nj][1], v2 = S[nj][2], v3 = S[nj][3];
                if (s > t0 || v0 == 0.f) v0 = -INFINITY;
                if (s + 1 > t0 || v1 == 0.f) v1 = -INFINITY;
                if (s > t1 || v2 == 0.f) v2 = -INFINITY;
                if (s + 1 > t1 || v3 == 0.f) v3 = -INFINITY;
                S[nj][0] = v0; S[nj][1] = v1; S[nj][2] = v2; S[nj][3] = v3;
                mx0 = fmaxf(mx0, fmaxf(v0, v1));
                mx1 = fmaxf(mx1, fmaxf(v2, v3));
            }
            mx0 = fmaxf(mx0, __shfl_xor_sync(~0u, mx0, 1));
            mx0 = fmaxf(mx0, __shfl_xor_sync(~0u, mx0, 2));
            mx1 = fmaxf(mx1, __shfl_xor_sync(~0u, mx1, 1));
            mx1 = fmaxf(mx1, __shfl_xor_sync(~0u, mx1, 2));

            float mn0 = fmaxf(m0, mx0), mn1 = fmaxf(m1, mx1);
            float c0 = __expf(mclamp(m0) - mclamp(mn0));
            float c1 = __expf(mclamp(m1) - mclamp(mn1));
            float me0 = mclamp(mn0), me1 = mclamp(mn1);

            float rs0 = 0.f, rs1 = 0.f;
#pragma unroll
            for (int nj = 0; nj < 8; nj++) {
                float p0 = __expf(S[nj][0] - me0);
                float p1 = __expf(S[nj][1] - me0);
                float p2 = __expf(S[nj][2] - me1);
                float p3 = __expf(S[nj][3] - me1);
                S[nj][0] = p0; S[nj][1] = p1; S[nj][2] = p2; S[nj][3] = p3;
                rs0 += p0 + p1; rs1 += p2 + p3;
            }
            rs0 += __shfl_xor_sync(~0u, rs0, 1); rs0 += __shfl_xor_sync(~0u, rs0, 2);
            rs1 += __shfl_xor_sync(~0u, rs1, 1); rs1 += __shfl_xor_sync(~0u, rs1, 2);
            l0 = l0 * c0 + rs0; l1 = l1 * c1 + rs1;
            m0 = mn0; m1 = mn1;

#pragma unroll
            for (int d = 0; d < 8; d++) {
                O[d][0] *= c0; O[d][1] *= c0;
                O[d][2] *= c1; O[d][3] *= c1;
            }

#pragma unroll
            for (int sk = 0; sk < 4; sk++) {
                uint32_t aH[4], aL[4];
                aH[0] = hpack(S[2 * sk][0], S[2 * sk][1]);
                aH[1] = hpack(S[2 * sk][2], S[2 * sk][3]);
                aH[2] = hpack(S[2 * sk + 1][0], S[2 * sk + 1][1]);
                aH[3] = hpack(S[2 * sk + 1][2], S[2 * sk + 1][3]);
                aL[0] = lpack(S[2 * sk][0], S[2 * sk][1]);
                aL[1] = lpack(S[2 * sk][2], S[2 * sk][3]);
                aL[2] = lpack(S[2 * sk + 1][0], S[2 * sk + 1][1]);
                aL[3] = lpack(S[2 * sk + 1][2], S[2 * sk + 1][3]);
#pragma unroll
                for (int djp = 0; djp < 4; djp++) {
                    int r = sk * 16 + (lane & 15);
                    int c16 = djp * 2 + (lane >> 4);
                    uint32_t v0, v1, v2, v3;
                    LDSM4T(v0, v1, v2, v3, sb + swz8(FSVH, r, c16));
                    MMAF16(O[2 * djp], aH, v0, v1);
                    MMAF16(O[2 * djp + 1], aH, v2, v3);
                    MMAF16(O[2 * djp], aL, v0, v1);
                    MMAF16(O[2 * djp + 1], aL, v2, v3);
                    uint32_t w0, w1, w2, w3;
                    LDSM4T(w0, w1, w2, w3, sb + swz8(FSVL, r, c16));
                    MMAF16(O[2 * djp], aH, w0, w1);
                    MMAF16(O[2 * djp + 1], aH, w2, w3);
                }
            }
        }
        __syncthreads();
    }

    float inv0 = 1.f / (l0 * 8.0f);
    float inv1 = 1.f / (l1 * 8.0f);
    size_t r0 = (size_t)(b * PT + t0) * PE + h * PD;
    size_t r1 = (size_t)(b * PT + t1) * PE + h * PD;
#pragma unroll
    for (int dj = 0; dj < 8; dj++) {
        int c = dj * 8 + 2 * tg;
        *(uint32_t*)(oh + r0 + c) = hpack(O[dj][0] * inv0, O[dj][1] * inv0);
        *(uint32_t*)(oh + r1 + c) = hpack(O[dj][2] * inv1, O[dj][3] * inv1);
    }
}

// ---------------- loss: merge fused lse partials ----------------
__global__ __launch_bounds__(256)
void lse_reduce(const float2* __restrict__ lsep, const float* __restrict__ logits,
                const int* __restrict__ targets, float* __restrict__ rowloss)
{
    __shared__ float smx[256], ssx[256];
    int row = blockIdx.x, tid = threadIdx.x;
    const float2* pr = lsep + (size_t)row * NB4;
    float m = -INFINITY, s = 0.f;
    for (int i = tid; i < NB4; i += 256) {
        float2 p = pr[i];
        float mm = fmaxf(m, p.x);
        s = s * __expf(m - mm) + p.y * __expf(p.x - mm);
        m = mm;
    }
    smx[tid] = m; ssx[tid] = s; __syncthreads();
    for (int k = 128; k > 0; k >>= 1) {
        if (tid < k) {
            float m1 = smx[tid], s1 = ssx[tid], m2 = smx[tid + k], s2 = ssx[tid + k];
            float mm = fmaxf(m1, m2);
            smx[tid] = mm;
            ssx[tid] = s1 * __expf(m1 - mm) + s2 * __expf(m2 - mm);
        }
        __syncthreads();
    }
    if (tid == 0) {
        float lse = smx[0] + logf(ssx[0]);
        rowloss[row] = -(logits[(size_t)row * PV + targets[row]] - lse);
    }
}

__global__ __launch_bounds__(256)
void finloss_kernel(const float* __restrict__ rowloss, float* __restrict__ out_loss)
{
    __shared__ float red[256];
    int tid = threadIdx.x;
    float s = 0.f;
    for (int i = tid; i < PM; i += 256) s += rowloss[i];
    red[tid] = s; __syncthreads();
    for (int k = 128; k > 0; k >>= 1) { if (tid < k) red[tid] += red[tid+k]; __syncthreads(); }
    if (tid == 0) out_loss[0] = red[0] / (float)PM;
}

// ---------------- launch ----------------
extern "C" void kernel_launch(void* const* d_in, const int* in_sizes, int n_in,
                              void* d_out, int out_size)
{
    const int*   tokens    = (const int*)d_in[0];
    const int*   targets   = (const int*)d_in[1];
    const float* tok_table = (const float*)d_in[2];
    const float* pos_emb   = (const float*)d_in[3];
    const float* Wq = (const float*)d_in[4];  const float* bq = (const float*)d_in[5];
    const float* Wk = (const float*)d_in[6];  const float* bk = (const float*)d_in[7];
    const float* Wv = (const float*)d_in[8];  const float* bv = (const float*)d_in[9];
    const float* Wo = (const float*)d_in[10]; const float* bo = (const float*)d_in[11];
    float* out = (float*)d_out;

    __half *xh, *xl, *wqkv, *wo, *oh, *qh, *kh, *vh, *vl;
    float *qkv, *b3, *rl;
    float2 *lp;
    cudaGetSymbolAddress((void**)&xh,   g_xh);
    cudaGetSymbolAddress((void**)&xl,   g_xl);
    cudaGetSymbolAddress((void**)&wqkv, g_wqkv);
    cudaGetSymbolAddress((void**)&wo,   g_wo);
    cudaGetSymbolAddress((void**)&oh,   g_oh);
    cudaGetSymbolAddress((void**)&qh,   g_qh);
    cudaGetSymbolAddress((void**)&kh,   g_kh);
    cudaGetSymbolAddress((void**)&vh,   g_vh);
    cudaGetSymbolAddress((void**)&vl,   g_vl);
    cudaGetSymbolAddress((void**)&qkv,  g_qkv);
    cudaGetSymbolAddress((void**)&b3,   g_bias3);
    cudaGetSymbolAddress((void**)&rl,   g_rowloss);
    cudaGetSymbolAddress((void**)&lp,   g_lsepart);

    cudaFuncSetAttribute(gemm_fp16_2p, cudaFuncAttributeMaxDynamicSharedMemorySize, GSMEM2);
    cudaFuncSetAttribute(gemm_fp16_1p, cudaFuncAttributeMaxDynamicSharedMemorySize, GSMEM1);

    // 1) embed + fp16 hi/lo split of x
    embed_split<<<(PM * PE / 4) / 256, 256>>>(tokens, tok_table, pos_emb, xh, xl);

    // 2) weight converts + bias pack
    convW<<<(PE*PE/4)/256, 256>>>(Wq, wqkv,                   PE*PE/4);
    convW<<<(PE*PE/4)/256, 256>>>(Wk, wqkv + (size_t)PE*PE,   PE*PE/4);
    convW<<<(PE*PE/4)/256, 256>>>(Wv, wqkv + (size_t)2*PE*PE, PE*PE/4);
    convW<<<(int)(((size_t)PV*PE/4)/256), 256>>>(Wo, wo, (int)((size_t)PV*PE/4));
    pack_bias<<<QKVN/256, 256>>>(bq, bk, bv, b3);

    // 3) fused QKV GEMM (4-warp 64x64, 2-product split-A)
    gemm_fp16_2p<<<dim3(PM/BM, QKVN/BN), 128, GSMEM2>>>(xh, xl, wqkv, b3, qkv, QKVN);

    // 3b) one-time qkv -> fp16 planes (kills 8.5x redundant staging converts)
    qkv_split<<<(PM * PE / 4) / 256, 256>>>(qkv, qh, kh, vh, vl);

    // 4) tensor-core flash attention over fp16 planes -> oh
    attn_tc<<<dim3(PT/FA_QB, PB*PH), 256>>>(qh, kh, vh, vl, oh);

    // 5) logits GEMM (4-warp 64x64 + fused lse, streaming stores) -> d_out
    gemm_fp16_1p<<<dim3(PM/BM, PV/BN), 128, GSMEM1>>>(oh, wo, bo, out, lp);

    // 6) loss from partials
    if ((size_t)out_size > BTV) {
        lse_reduce<<<PM, 256>>>(lp, out, targets, rl);
        finloss_kernel<<<1, 256>>>(rl, out + BTV);
    }
}

// round 17
// speedup vs baseline: 1.0264x; 1.0169x over previous
#include <cuda_runtime.h>
#include <cuda_fp16.h>
#include <math.h>
#include <cstdint>

// ---------------- problem constants ----------------
#define PB 2
#define PT 2048
#define PE 1024
#define PH 16
#define PD 64
#define PV 32000
#define PM (PB*PT)            // 4096
#define QKVN 3072
#define BTV ((size_t)PM*PV)
#define NBL (PV/128)          // 250 N-blocks in logits gemm
#define NB4 (NBL*2)           // 500 partials per row

// ---------------- scratch (__device__ globals) ----------------
__device__ __half g_xh[(size_t)PM*PE],  g_xl[(size_t)PM*PE];
__device__ __half g_wqkv[(size_t)QKVN*PE];
__device__ __half g_wo[(size_t)PV*PE];
__device__ __half g_oh[(size_t)PM*PE];
__device__ __half g_qh[(size_t)PM*PE];          // q fp16 plane
__device__ __half g_kh[(size_t)PM*PE];          // k fp16 plane
__device__ __half g_vh[(size_t)PM*PE];          // v hi plane
__device__ __half g_vl[(size_t)PM*PE];          // v lo plane
__device__ float  g_bias3[QKVN];
__device__ float  g_rowloss[PM];
__device__ float2 g_lsepart[(size_t)PM*NB4];

// ---------------- helpers ----------------
__device__ __forceinline__ uint32_t smem_u32(const void* p) {
    uint32_t a;
    asm("{ .reg .u64 t; cvta.to.shared.u64 t, %1; cvt.u32.u64 %0, t; }" : "=r"(a) : "l"(p));
    return a;
}
__device__ __forceinline__ void cp16(uint32_t dst, const void* src) {
    asm volatile("cp.async.cg.shared.global [%0], [%1], 16;" :: "r"(dst), "l"(src) : "memory");
}
#define CP_COMMIT() asm volatile("cp.async.commit_group;" ::: "memory")
#define CP_WAIT(n)  asm volatile("cp.async.wait_group %0;" :: "n"(n) : "memory")

#define LDSM4(r0,r1,r2,r3,addr) \
    asm volatile("ldmatrix.sync.aligned.m8n8.x4.shared.b16 {%0,%1,%2,%3}, [%4];" \
        : "=r"(r0),"=r"(r1),"=r"(r2),"=r"(r3) : "r"(addr))
#define LDSM4T(r0,r1,r2,r3,addr) \
    asm volatile("ldmatrix.sync.aligned.m8n8.x4.trans.shared.b16 {%0,%1,%2,%3}, [%4];" \
        : "=r"(r0),"=r"(r1),"=r"(r2),"=r"(r3) : "r"(addr))

#define MMAF16(c, a, b0, b1) \
    asm volatile("mma.sync.aligned.m16n8k16.row.col.f32.f16.f16.f32 " \
        "{%0,%1,%2,%3}, {%4,%5,%6,%7}, {%8,%9}, {%0,%1,%2,%3};" \
        : "+f"((c)[0]), "+f"((c)[1]), "+f"((c)[2]), "+f"((c)[3]) \
        : "r"((a)[0]), "r"((a)[1]), "r"((a)[2]), "r"((a)[3]), "r"(b0), "r"(b1))

__device__ __forceinline__ uint32_t hpack(float x, float y) {
    __half2 h = __floats2half2_rn(x, y);
    return *(uint32_t*)&h;
}
__device__ __forceinline__ uint32_t lpack(float x, float y) {
    float hx = __half2float(__float2half(x));
    float hy = __half2float(__float2half(y));
    __half2 h = __floats2half2_rn(x - hx, y - hy);
    return *(uint32_t*)&h;
}

// ---------------- embed + fp16 hi/lo split ----------------
__global__ void embed_split(const int* __restrict__ tokens,
                            const float* __restrict__ tok_table,
                            const float* __restrict__ pos_emb,
                            __half* __restrict__ xh, __half* __restrict__ xl)
{
    int i4 = blockIdx.x * blockDim.x + threadIdx.x;
    int row = i4 >> 8, e4 = i4 & 255;
    int t = row & (PT - 1);
    float4 a = *(const float4*)(tok_table + (size_t)tokens[row] * PE + e4 * 4);
    float4 b = *(const float4*)(pos_emb + (size_t)t * PE + e4 * 4);
    float x0 = a.x + b.x, x1 = a.y + b.y, x2 = a.z + b.z, x3 = a.w + b.w;
    ((uint2*)xh)[i4] = make_uint2(hpack(x0, x1), hpack(x2, x3));
    ((uint2*)xl)[i4] = make_uint2(lpack(x0, x1), lpack(x2, x3));
}

__global__ void convW(const float* __restrict__ src, __half* __restrict__ dst, int n4)
{
    int i4 = blockIdx.x * blockDim.x + threadIdx.x;
    if (i4 >= n4) return;
    float4 v = ((const float4*)src)[i4];
    ((uint2*)dst)[i4] = make_uint2(hpack(v.x, v.y), hpack(v.z, v.w));
}

// one launch converts Wq|Wk|Wv into stacked wqkv
__global__ void convW3(const float* __restrict__ Wq, const float* __restrict__ Wk,
                       const float* __restrict__ Wv, __half* __restrict__ dst)
{
    int i4 = blockIdx.x * blockDim.x + threadIdx.x;   // over 3*PE*PE/4
    int seg = i4 >> 18;                               // PE*PE/4 = 262144 per segment
    int off = i4 & 262143;
    const float* src = (seg == 0 ? Wq : (seg == 1 ? Wk : Wv));
    float4 v = ((const float4*)src)[off];
    ((uint2*)dst)[i4] = make_uint2(hpack(v.x, v.y), hpack(v.z, v.w));
}

__global__ void pack_bias(const float* __restrict__ bq, const float* __restrict__ bk,
                          const float* __restrict__ bv, float* __restrict__ b3)
{
    int i = blockIdx.x * blockDim.x + threadIdx.x;
    if (i < 1024)       b3[i] = bq[i];
    else if (i < 2048)  b3[i] = bk[i - 1024];
    else if (i < QKVN)  b3[i] = bv[i - 2048];
}

// ---------------- common config ----------------
#define BM 128
#define BN 128
#define BK 32
#define KE 1024
#define STAGES 4
#define TILE_B (BM*BK*2)
#define NCHUNK (KE/BK)
__device__ __forceinline__ uint32_t swz(uint32_t base, int r, int c16) {
    return base + r * 64 + ((c16 ^ ((r >> 1) & 3)) << 4);
}

// ---------------- QKV GEMM: 4 warps, 64x64 warp tile, fused fp16-plane epilogue ------
#define SSTAGE2 (3*TILE_B)
#define GSMEM2 (STAGES*SSTAGE2)

__global__ __launch_bounds__(128, 2)
void gemm_fp16_2p(const __half* __restrict__ Ah, const __half* __restrict__ Al,
                  const __half* __restrict__ Bw, const float* __restrict__ bias,
                  __half* __restrict__ qh, __half* __restrict__ kh,
                  __half* __restrict__ vh, __half* __restrict__ vl)
{
    extern __shared__ char smem[];
    uint32_t sb = smem_u32(smem);
    int tid = threadIdx.x;
    int lane = tid & 31, wid = tid >> 5;
    int wm = wid >> 1, wn = wid & 1;         // 2 x 2 warps, warp tile 64 x 64
    int row0 = blockIdx.x * BM;
    int col0 = blockIdx.y * BN;

    const __half* Ahg = Ah + (size_t)row0 * KE;
    const __half* Alg = Al + (size_t)row0 * KE;
    const __half* Bg  = Bw + (size_t)col0 * KE;

    float acc[4][8][4];
#pragma unroll
    for (int i = 0; i < 4; i++)
#pragma unroll
        for (int j = 0; j < 8; j++)
#pragma unroll
            for (int q = 0; q < 4; q++) acc[i][j][q] = 0.f;

#define STAGE_LOAD2(stageBase, k0)                                             \
    do {                                                                       \
        _Pragma("unroll")                                                      \
        for (int j = 0; j < 12; j++) {                                         \
            int u = tid + 128 * j;                                             \
            int p = u >> 9, ix = u & 511;                                      \
            int r = ix >> 2, c16 = ix & 3;                                     \
            const __half* src = (p == 0 ? Ahg : (p == 1 ? Alg : Bg));          \
            cp16(swz(sb + (stageBase), r, c16) + p * TILE_B,                   \
                 src + (size_t)r * KE + (k0) + c16 * 8);                       \
        }                                                                      \
    } while (0)

#pragma unroll
    for (int s = 0; s < STAGES - 1; s++) {
        STAGE_LOAD2(s * SSTAGE2, s * BK);
        CP_COMMIT();
    }

    for (int kt = 0; kt < NCHUNK; kt++) {
        CP_WAIT(STAGES - 2);
        __syncthreads();
        int pf = kt + STAGES - 1;
        if (pf < NCHUNK) STAGE_LOAD2((pf & (STAGES - 1)) * SSTAGE2, pf * BK);
        CP_COMMIT();

        uint32_t stB = sb + (kt & (STAGES - 1)) * SSTAGE2;
        uint32_t aHB = stB, aLB = stB + TILE_B, bB = stB + 2 * TILE_B;
#pragma unroll
        for (int ks = 0; ks < 2; ks++) {
            uint32_t rb[4][4];
#pragma unroll
            for (int ni = 0; ni < 4; ni++) {
                int r = wn * 64 + ni * 16 + (lane & 7) + ((lane >> 4) & 1) * 8;
                int c16 = ks * 2 + ((lane >> 3) & 1);
                LDSM4(rb[ni][0], rb[ni][1], rb[ni][2], rb[ni][3], swz(bB, r, c16));
            }
            int ar = wm * 64 + (lane & 15);
            int ac16 = ks * 2 + (lane >> 4);
            uint32_t raH[4][4], raL[4][4];
#pragma unroll
            for (int mi = 0; mi < 4; mi++) {
                LDSM4(raH[mi][0], raH[mi][1], raH[mi][2], raH[mi][3],
                      swz(aHB, ar + mi * 16, ac16));
                LDSM4(raL[mi][0], raL[mi][1], raL[mi][2], raL[mi][3],
                      swz(aLB, ar + mi * 16, ac16));
            }
#pragma unroll
            for (int mi = 0; mi < 4; mi++)
#pragma unroll
                for (int nj = 0; nj < 8; nj++) {
                    uint32_t b0 = rb[nj >> 1][(nj & 1) * 2];
                    uint32_t b1 = rb[nj >> 1][(nj & 1) * 2 + 1];
                    MMAF16(acc[mi][nj], raH[mi], b0, b1);
                    MMAF16(acc[mi][nj], raL[mi], b0, b1);
                }
        }
    }

    // epilogue: bias add + direct fp16 plane conversion (CTA band is wholly q, k, or v)
    int g = lane >> 2, tg = lane & 3;
    int region = col0 >> 10;                 // 0=q, 1=k, 2=v
    int cbase = col0 & 1023;                 // offset within the plane
    __half* dsth = (region == 0 ? qh : (region == 1 ? kh : vh));
#pragma unroll
    for (int mi = 0; mi < 4; mi++) {
        int r = row0 + wm * 64 + mi * 16 + g;
#pragma unroll
        for (int nj = 0; nj < 8; nj++) {
            int c = cbase + wn * 64 + nj * 8 + tg * 2;
            float bx = bias[col0 + wn * 64 + nj * 8 + tg * 2];
            float by = bias[col0 + wn * 64 + nj * 8 + tg * 2 + 1];
            float v0 = acc[mi][nj][0] + bx, v1 = acc[mi][nj][1] + by;
            float v2 = acc[mi][nj][2] + bx, v3 = acc[mi][nj][3] + by;
            *(uint32_t*)(dsth + (size_t)r * PE + c) = hpack(v0, v1);
            *(uint32_t*)(dsth + (size_t)(r + 8) * PE + c) = hpack(v2, v3);
            if (region == 2) {
                *(uint32_t*)(vl + (size_t)r * PE + c) = lpack(v0, v1);
                *(uint32_t*)(vl + (size_t)(r + 8) * PE + c) = lpack(v2, v3);
            }
        }
    }
}

// ---------------- logits GEMM: 128x128 CTA, 4 warps, 64x64 warp tile, fused lse ----------
#define SSTAGE1 (2*TILE_B)
#define GSMEM1 (STAGES*SSTAGE1)     // 65536

__global__ __launch_bounds__(128, 2)
void gemm_fp16_1p(const __half* __restrict__ Aw, const __half* __restrict__ Bw,
                  const float* __restrict__ bias, float* __restrict__ C,
                  float2* __restrict__ lsep)
{
    extern __shared__ char smem[];
    uint32_t sb = smem_u32(smem);
    int tid = threadIdx.x;
    int lane = tid & 31, wid = tid >> 5;
    int wm = wid >> 1, wn = wid & 1;          // 2 x 2 warps, warp tile 64 x 64
    int row0 = blockIdx.x * BM;
    int col0 = blockIdx.y * BN;

    const __half* Ag = Aw + (size_t)row0 * KE;
    const __half* Bg = Bw + (size_t)col0 * KE;

    float acc[4][8][4];
#pragma unroll
    for (int i = 0; i < 4; i++)
#pragma unroll
        for (int j = 0; j < 8; j++)
#pragma unroll
            for (int q = 0; q < 4; q++) acc[i][j][q] = 0.f;

#define STAGE_LOAD1(stageBase, k0)                                             \
    do {                                                                       \
        _Pragma("unroll")                                                      \
        for (int j = 0; j < 8; j++) {                                          \
            int u = tid + 128 * j;                                             \
            int p = u >> 9, ix = u & 511;                                      \
            int r = ix >> 2, c16 = ix & 3;                                     \
            const __half* src = (p == 0 ? Ag : Bg);                            \
            cp16(swz(sb + (stageBase), r, c16) + p * TILE_B,                   \
                 src + (size_t)r * KE + (k0) + c16 * 8);                       \
        }                                                                      \
    } while (0)

#pragma unroll
    for (int s = 0; s < STAGES - 1; s++) {
        STAGE_LOAD1(s * SSTAGE1, s * BK);
        CP_COMMIT();
    }

    for (int kt = 0; kt < NCHUNK; kt++) {
        CP_WAIT(STAGES - 2);
        __syncthreads();
        int pf = kt + STAGES - 1;
        if (pf < NCHUNK) STAGE_LOAD1((pf & (STAGES - 1)) * SSTAGE1, pf * BK);
        CP_COMMIT();

        uint32_t stB = sb + (kt & (STAGES - 1)) * SSTAGE1;
        uint32_t aB = stB, bB = stB + TILE_B;
#pragma unroll
        for (int ks = 0; ks < 2; ks++) {
            uint32_t rb[4][4];
#pragma unroll
            for (int ni = 0; ni < 4; ni++) {
                int r = wn * 64 + ni * 16 + (lane & 7) + ((lane >> 4) & 1) * 8;
                int c16 = ks * 2 + ((lane >> 3) & 1);
                LDSM4(rb[ni][0], rb[ni][1], rb[ni][2], rb[ni][3], swz(bB, r, c16));
            }
            uint32_t ra[4][4];
            int ar = wm * 64 + (lane & 15);
            int ac16 = ks * 2 + (lane >> 4);
#pragma unroll
            for (int mi = 0; mi < 4; mi++)
                LDSM4(ra[mi][0], ra[mi][1], ra[mi][2], ra[mi][3],
                      swz(aB, ar + mi * 16, ac16));
#pragma unroll
            for (int mi = 0; mi < 4; mi++)
#pragma unroll
                for (int nj = 0; nj < 8; nj++)
                    MMAF16(acc[mi][nj], ra[mi],
                           rb[nj >> 1][(nj & 1) * 2], rb[nj >> 1][(nj & 1) * 2 + 1]);
        }
    }

    // epilogue: bias add, streaming store, fused per-row lse partial (64-col band)
    int g = lane >> 2, tg = lane & 3;
    int pslot = blockIdx.y * 2 + wn;
#pragma unroll
    for (int mi = 0; mi < 4; mi++) {
        int r = row0 + wm * 64 + mi * 16 + g;
        float m0 = -INFINITY, m1 = -INFINITY;
#pragma unroll
        for (int nj = 0; nj < 8; nj++) {
            int c = col0 + wn * 64 + nj * 8 + tg * 2;
            float bx = bias[c], by = bias[c + 1];
            float v0 = acc[mi][nj][0] + bx, v1 = acc[mi][nj][1] + by;
            float v2 = acc[mi][nj][2] + bx, v3 = acc[mi][nj][3] + by;
            acc[mi][nj][0] = v0; acc[mi][nj][1] = v1;
            acc[mi][nj][2] = v2; acc[mi][nj][3] = v3;
            __stcs((float2*)(C + (size_t)r * PV + c), make_float2(v0, v1));
            __stcs((float2*)(C + (size_t)(r + 8) * PV + c), make_float2(v2, v3));
            m0 = fmaxf(m0, fmaxf(v0, v1));
            m1 = fmaxf(m1, fmaxf(v2, v3));
        }
        m0 = fmaxf(m0, __shfl_xor_sync(~0u, m0, 1));
        m0 = fmaxf(m0, __shfl_xor_sync(~0u, m0, 2));
        m1 = fmaxf(m1, __shfl_xor_sync(~0u, m1, 1));
        m1 = fmaxf(m1, __shfl_xor_sync(~0u, m1, 2));
        float s0 = 0.f, s1 = 0.f;
#pragma unroll
        for (int nj = 0; nj < 8; nj++) {
            s0 += __expf(acc[mi][nj][0] - m0) + __expf(acc[mi][nj][1] - m0);
            s1 += __expf(acc[mi][nj][2] - m1) + __expf(acc[mi][nj][3] - m1);
        }
        s0 += __shfl_xor_sync(~0u, s0, 1); s0 += __shfl_xor_sync(~0u, s0, 2);
        s1 += __shfl_xor_sync(~0u, s1, 1); s1 += __shfl_xor_sync(~0u, s1, 2);
        if (tg == 0) {
            lsep[(size_t)r * NB4 + pslot] = make_float2(m0, s0);
            lsep[(size_t)(r + 8) * NB4 + pslot] = make_float2(m1, s1);
        }
    }
}

// ---------------- tensor-core flash attention (fp16 plane staging) ----------------
#define FA_QB 128
#define FA_KB 64
#define FSQ 0
#define FSK 16384
#define FSVH 24576
#define FSVL 32768
#define FSMEM 40960

__device__ __forceinline__ uint32_t swz8(uint32_t base, int r, int c16) {
    return base + r * 128 + ((c16 ^ (r & 7)) << 4);
}
__device__ __forceinline__ float mclamp(float x) { return fmaxf(x, -1e30f); }

__global__ __launch_bounds__(256, 2)
void attn_tc(const __half* __restrict__ qh, const __half* __restrict__ kh,
             const __half* __restrict__ vh, const __half* __restrict__ vl,
             __half* __restrict__ oh)
{
    __shared__ __align__(1024) char sm[FSMEM];
    uint32_t sb = smem_u32(sm);
    int tid = threadIdx.x;
    int lane = tid & 31, w = tid >> 5;
    int g = lane >> 2, tg = lane & 3;
    int bh = blockIdx.y;
    int b = bh >> 4, h = bh & 15;
    int q0 = (gridDim.x - 1 - blockIdx.x) * FA_QB;   // heaviest blocks first

    const __half* qb = qh + ((size_t)b * PT) * PE + h * PD;
    const __half* kb = kh + ((size_t)b * PT) * PE + h * PD;
    const __half* vhb = vh + ((size_t)b * PT) * PE + h * PD;
    const __half* vlb = vl + ((size_t)b * PT) * PE + h * PD;

#pragma unroll
    for (int j = 0; j < 4; j++) {
        int u = tid + 256 * j;
        int r = u >> 3, c8 = u & 7;
        uint4 v = *(const uint4*)(qb + (size_t)(q0 + r) * PE + c8 * 8);
        *(uint4*)(sm + swz8(FSQ, r, c8)) = v;
    }
    __syncthreads();

    uint32_t qf[4][4];
#pragma unroll
    for (int kk = 0; kk < 4; kk++) {
        int r = w * 16 + (lane & 15);
        int c16 = kk * 2 + (lane >> 4);
        LDSM4(qf[kk][0], qf[kk][1], qf[kk][2], qf[kk][3], sb + swz8(FSQ, r, c16));
    }
    __syncthreads();

    float O[8][4];
#pragma unroll
    for (int d = 0; d < 8; d++)
#pragma unroll
        for (int q = 0; q < 4; q++) O[d][q] = 0.f;
    float m0 = -INFINITY, m1 = -INFINITY, l0 = 0.f, l1 = 0.f;

    int t0 = q0 + w * 16 + g;
    int t1 = t0 + 8;
    int tmaxw = q0 + w * 16 + 15;
    int nkt = q0 / FA_KB + 2;

    for (int kt = 0; kt < nkt; kt++) {
        int s0 = kt * FA_KB;
#pragma unroll
        for (int j = 0; j < 6; j++) {
            int u = tid + 256 * j;
            int p = u >> 9, ix = u & 511;
            int r = ix >> 3, c8 = ix & 7;
            const __half* src = (p == 0 ? kb : (p == 1 ? vhb : vlb));
            uint4 v = *(const uint4*)(src + (size_t)(s0 + r) * PE + c8 * 8);
            *(uint4*)(sm + swz8(FSK + p * 8192, r, c8)) = v;
        }
        __syncthreads();

        if (s0 <= tmaxw) {
            float S[8][4];
#pragma unroll
            for (int nj = 0; nj < 8; nj++)
#pragma unroll
                for (int q = 0; q < 4; q++) S[nj][q] = 0.f;
#pragma unroll
            for (int njp = 0; njp < 4; njp++) {
#pragma unroll
                for (int kk = 0; kk < 4; kk++) {
                    uint32_t b0, b1, b2, b3;
                    int r = njp * 16 + (lane & 7) + ((lane >> 4) & 1) * 8;
                    int c16 = kk * 2 + ((lane >> 3) & 1);
                    LDSM4(b0, b1, b2, b3, sb + swz8(FSK, r, c16));
                    MMAF16(S[2 * njp], qf[kk], b0, b1);
                    MMAF16(S[2 * njp + 1], qf[kk], b2, b3);
                }
            }
            float mx0 = -INFINITY, mx1 = -INFINITY;
#pragma unroll
            for (int nj = 0; nj < 8; nj++) {
                int s = s0 + nj * 8 + 2 * tg;
                float v0 = S[nj][0], v1 = S[nj][1], v2 = S[nj][2], v3 = S[nj][3];
                if (s > t0 || v0 == 0.f) v0 = -INFINITY;
                if (s + 1 > t0 || v1 == 0.f) v1 = -INFINITY;
                if (s > t1 || v2 == 0.f) v2 = -INFINITY;
                if (s + 1 > t1 || v3 == 0.f) v3 = -INFINITY;
                S[nj][0] = v0; S[nj][1] = v1; S[nj][2] = v2; S[nj][3] = v3;
                mx0 = fmaxf(mx0, fmaxf(v0, v1));
                mx1 = fmaxf(mx1, fmaxf(v2, v3));
            }
            mx0 = fmaxf(mx0, __shfl_xor_sync(~0u, mx0, 1));
            mx0 = fmaxf(mx0, __shfl_xor_sync(~0u, mx0, 2));
            mx1 = fmaxf(mx1, __shfl_xor_sync(~0u, mx1, 1));
            mx1 = fmaxf(mx1, __shfl_xor_sync(~0u, mx1, 2));

            float mn0 = fmaxf(m0, mx0), mn1 = fmaxf(m1, mx1);
            float c0 = __expf(mclamp(m0) - mclamp(mn0));
            float c1 = __expf(mclamp(m1) - mclamp(mn1));
            float me0 = mclamp(mn0), me1 = mclamp(mn1);

            float rs0 = 0.f, rs1 = 0.f;
#pragma unroll
            for (int nj = 0; nj < 8; nj++) {
                float p0 = __expf(S[nj][0] - me0);
                float p1 = __expf(S[nj][1] - me0);
                float p2 = __expf(S[nj][2] - me1);
                float p3 = __expf(S[nj][3] - me1);
                S[nj][0] = p0; S[nj][1] = p1; S[nj][2] = p2; S[nj][3] = p3;
                rs0 += p0 + p1; rs1 += p2 + p3;
            }
            rs0 += __shfl_xor_sync(~0u, rs0, 1); rs0 += __shfl_xor_sync(~0u, rs0, 2);
            rs1 += __shfl_xor_sync(~0u, rs1, 1); rs1 += __shfl_xor_sync(~0u, rs1, 2);
            l0 = l0 * c0 + rs0; l1 = l1 * c1 + rs1;
            m0 = mn0; m1 = mn1;

#pragma unroll
            for (int d = 0; d < 8; d++) {
                O[d][0] *= c0; O[d][1] *= c0;
                O[d][2] *= c1; O[d][3] *= c1;
            }

#pragma unroll
            for (int sk = 0; sk < 4; sk++) {
                uint32_t aH[4], aL[4];
                aH[0] = hpack(S[2 * sk][0], S[2 * sk][1]);
                aH[1] = hpack(S[2 * sk][2], S[2 * sk][3]);
                aH[2] = hpack(S[2 * sk + 1][0], S[2 * sk + 1][1]);
                aH[3] = hpack(S[2 * sk + 1][2], S[2 * sk + 1][3]);
                aL[0] = lpack(S[2 * sk][0], S[2 * sk][1]);
                aL[1] = lpack(S[2 * sk][2], S[2 * sk][3]);
                aL[2] = lpack(S[2 * sk + 1][0], S[2 * sk + 1][1]);
                aL[3] = lpack(S[2 * sk + 1][2], S[2 * sk + 1][3]);
#pragma unroll
                for (int djp = 0; djp < 4; djp++) {
                    int r = sk * 16 + (lane & 15);
                    int c16 = djp * 2 + (lane >> 4);
                    uint32_t v0, v1, v2, v3;
                    LDSM4T(v0, v1, v2, v3, sb + swz8(FSVH, r, c16));
                    MMAF16(O[2 * djp], aH, v0, v1);
                    MMAF16(O[2 * djp + 1], aH, v2, v3);
                    MMAF16(O[2 * djp], aL, v0, v1);
                    MMAF16(O[2 * djp + 1], aL, v2, v3);
                    uint32_t w0, w1, w2, w3;
                    LDSM4T(w0, w1, w2, w3, sb + swz8(FSVL, r, c16));
                    MMAF16(O[2 * djp], aH, w0, w1);
                    MMAF16(O[2 * djp + 1], aH, w2, w3);
                }
            }
        }
        __syncthreads();
    }

    float inv0 = 1.f / (l0 * 8.0f);
    float inv1 = 1.f / (l1 * 8.0f);
    size_t r0 = (size_t)(b * PT + t0) * PE + h * PD;
    size_t r1 = (size_t)(b * PT + t1) * PE + h * PD;
#pragma unroll
    for (int dj = 0; dj < 8; dj++) {
        int c = dj * 8 + 2 * tg;
        *(uint32_t*)(oh + r0 + c) = hpack(O[dj][0] * inv0, O[dj][1] * inv0);
        *(uint32_t*)(oh + r1 + c) = hpack(O[dj][2] * inv1, O[dj][3] * inv1);
    }
}

// ---------------- loss: merge fused lse partials ----------------
__global__ __launch_bounds__(256)
void lse_reduce(const float2* __restrict__ lsep, const float* __restrict__ logits,
                const int* __restrict__ targets, float* __restrict__ rowloss)
{
    __shared__ float smx[256], ssx[256];
    int row = blockIdx.x, tid = threadIdx.x;
    const float2* pr = lsep + (size_t)row * NB4;
    float m = -INFINITY, s = 0.f;
    for (int i = tid; i < NB4; i += 256) {
        float2 p = pr[i];
        float mm = fmaxf(m, p.x);
        s = s * __expf(m - mm) + p.y * __expf(p.x - mm);
        m = mm;
    }
    smx[tid] = m; ssx[tid] = s; __syncthreads();
    for (int k = 128; k > 0; k >>= 1) {
        if (tid < k) {
            float m1 = smx[tid], s1 = ssx[tid], m2 = smx[tid + k], s2 = ssx[tid + k];
            float mm = fmaxf(m1, m2);
            smx[tid] = mm;
            ssx[tid] = s1 * __expf(m1 - mm) + s2 * __expf(m2 - mm);
        }
        __syncthreads();
    }
    if (tid == 0) {
        float lse = smx[0] + logf(ssx[0]);
        rowloss[row] = -(logits[(size_t)row * PV + targets[row]] - lse);
    }
}

__global__ __launch_bounds__(256)
void finloss_kernel(const float* __restrict__ rowloss, float* __restrict__ out_loss)
{
    __shared__ float red[256];
    int tid = threadIdx.x;
    float s = 0.f;
    for (int i = tid; i < PM; i += 256) s += rowloss[i];
    red[tid] = s; __syncthreads();
    for (int k = 128; k > 0; k >>= 1) { if (tid < k) red[tid] += red[tid+k]; __syncthreads(); }
    if (tid == 0) out_loss[0] = red[0] / (float)PM;
}

// ---------------- launch ----------------
extern "C" void kernel_launch(void* const* d_in, const int* in_sizes, int n_in,
                              void* d_out, int out_size)
{
    const int*   tokens    = (const int*)d_in[0];
    const int*   targets   = (const int*)d_in[1];
    const float* tok_table = (const float*)d_in[2];
    const float* pos_emb   = (const float*)d_in[3];
    const float* Wq = (const float*)d_in[4];  const float* bq = (const float*)d_in[5];
    const float* Wk = (const float*)d_in[6];  const float* bk = (const float*)d_in[7];
    const float* Wv = (const float*)d_in[8];  const float* bv = (const float*)d_in[9];
    const float* Wo = (const float*)d_in[10]; const float* bo = (const float*)d_in[11];
    float* out = (float*)d_out;

    __half *xh, *xl, *wqkv, *wo, *oh, *qh, *kh, *vh, *vl;
    float *b3, *rl;
    float2 *lp;
    cudaGetSymbolAddress((void**)&xh,   g_xh);
    cudaGetSymbolAddress((void**)&xl,   g_xl);
    cudaGetSymbolAddress((void**)&wqkv, g_wqkv);
    cudaGetSymbolAddress((void**)&wo,   g_wo);
    cudaGetSymbolAddress((void**)&oh,   g_oh);
    cudaGetSymbolAddress((void**)&qh,   g_qh);
    cudaGetSymbolAddress((void**)&kh,   g_kh);
    cudaGetSymbolAddress((void**)&vh,   g_vh);
    cudaGetSymbolAddress((void**)&vl,   g_vl);
    cudaGetSymbolAddress((void**)&b3,   g_bias3);
    cudaGetSymbolAddress((void**)&rl,   g_rowloss);
    cudaGetSymbolAddress((void**)&lp,   g_lsepart);

    cudaFuncSetAttribute(gemm_fp16_2p, cudaFuncAttributeMaxDynamicSharedMemorySize, GSMEM2);
    cudaFuncSetAttribute(gemm_fp16_1p, cudaFuncAttributeMaxDynamicSharedMemorySize, GSMEM1);

    // 1) embed + fp16 hi/lo split of x
    embed_split<<<(PM * PE / 4) / 256, 256>>>(tokens, tok_table, pos_emb, xh, xl);

    // 2) weight converts (fused qkv convert) + bias pack
    convW3<<<(3*PE*PE/4)/256, 256>>>(Wq, Wk, Wv, wqkv);
    convW<<<(int)(((size_t)PV*PE/4)/256), 256>>>(Wo, wo, (int)((size_t)PV*PE/4));
    pack_bias<<<QKVN/256, 256>>>(bq, bk, bv, b3);

    // 3) fused QKV GEMM -> fp16 q/k/vh/vl planes directly (no fp32 intermediate)
    gemm_fp16_2p<<<dim3(PM/BM, QKVN/BN), 128, GSMEM2>>>(xh, xl, wqkv, b3, qh, kh, vh, vl);

    // 4) tensor-core flash attention over fp16 planes -> oh
    attn_tc<<<dim3(PT/FA_QB, PB*PH), 256>>>(qh, kh, vh, vl, oh);

    // 5) logits GEMM (4-warp 64x64 + fused lse, streaming stores) -> d_out
    gemm_fp16_1p<<<dim3(PM/BM, PV/BN), 128, GSMEM1>>>(oh, wo, bo, out, lp);

    // 6) loss from partials
    if ((size_t)out_size > BTV) {
        lse_reduce<<<PM, 256>>>(lp, out, targets, rl);
        finloss_kernel<<<1, 256>>>(rl, out + BTV);
    }
}